// round 16
// baseline (speedup 1.0000x reference)
#include <cuda_runtime.h>
#include <cuda_fp16.h>
#include <math.h>

#define S_TOK 4032
#define DIMC  1536
#define NHEAD 12
#define HDIM  128
#define ROTC  64
#define FRAME 448

// Scratch (device globals)
__device__ float  g_q[S_TOK * DIMC];        // fp32 Q projection (pre-norm)
__device__ float  g_k[S_TOK * DIMC];        // fp32 K projection (pre-norm)
__device__ __half g_qh[S_TOK * DIMC];       // fp16 roped Q
__device__ __half g_kh[S_TOK * DIMC];       // fp16 roped K
__device__ __half g_v[S_TOK * DIMC];        // fp16 V
__device__ __half g_attn[S_TOK * DIMC];     // fp16 attention output
__device__ __half g_xh[S_TOK * DIMC];       // fp16 x
__device__ __half g_wq[DIMC * DIMC];        // fp16 weights, TRANSPOSED [n][k]
__device__ __half g_wk[DIMC * DIMC];
__device__ __half g_wv[DIMC * DIMC];
__device__ __half g_wo[DIMC * DIMC];

// ---------------------------------------------------------------------------
// fp16 mma / ldmatrix / async helpers
// ---------------------------------------------------------------------------
__device__ __forceinline__ void mma_f16(float* d, const unsigned* a,
                                        unsigned b0, unsigned b1) {
    asm volatile(
        "mma.sync.aligned.m16n8k16.row.col.f32.f16.f16.f32 "
        "{%0,%1,%2,%3}, {%4,%5,%6,%7}, {%8,%9}, {%0,%1,%2,%3};\n"
        : "+f"(d[0]), "+f"(d[1]), "+f"(d[2]), "+f"(d[3])
        : "r"(a[0]), "r"(a[1]), "r"(a[2]), "r"(a[3]), "r"(b0), "r"(b1));
}
__device__ __forceinline__ void ldsm_x4(uint4& d, unsigned addr) {
    asm volatile("ldmatrix.sync.aligned.m8n8.x4.shared.b16 {%0,%1,%2,%3}, [%4];"
                 : "=r"(d.x), "=r"(d.y), "=r"(d.z), "=r"(d.w) : "r"(addr));
}
__device__ __forceinline__ void ldsm_x4_t(uint4& d, unsigned addr) {
    asm volatile("ldmatrix.sync.aligned.m8n8.x4.trans.shared.b16 {%0,%1,%2,%3}, [%4];"
                 : "=r"(d.x), "=r"(d.y), "=r"(d.z), "=r"(d.w) : "r"(addr));
}
__device__ __forceinline__ unsigned sptr(const void* p) {
    return (unsigned)__cvta_generic_to_shared(p);
}
#define CP16(dst, src) \
    asm volatile("cp.async.cg.shared.global [%0], [%1], 16;" :: "r"(dst), "l"(src))
#define CP_COMMIT() asm volatile("cp.async.commit_group;")
#define CP_WAIT(n)  asm volatile("cp.async.wait_group %0;" :: "n"(n))

// ---------------------------------------------------------------------------
// x: fp32 -> fp16 (elementwise)
// ---------------------------------------------------------------------------
__global__ void cvt_h_kernel(const float* __restrict__ src,
                             __half* __restrict__ dst, int n4)
{
    int i = blockIdx.x * blockDim.x + threadIdx.x;
    if (i < n4) {
        float4 v = ((const float4*)src)[i];
        ((__half2*)dst)[2 * i]     = __floats2half2_rn(v.x, v.y);
        ((__half2*)dst)[2 * i + 1] = __floats2half2_rn(v.z, v.w);
    }
}

// ---------------------------------------------------------------------------
// All 4 weights: transpose + fp16 in ONE launch. dst[n][k] = h(src[k][n]).
// ---------------------------------------------------------------------------
__global__ void cvt_tr4_kernel(const float* __restrict__ Wq,
                               const float* __restrict__ Wk,
                               const float* __restrict__ Wv,
                               const float* __restrict__ Wo,
                               __half* __restrict__ dq,
                               __half* __restrict__ dk,
                               __half* __restrict__ dv,
                               __half* __restrict__ dwo)
{
    __shared__ float tile[32][33];
    int z = blockIdx.z;
    const float* src = (z == 0) ? Wq : ((z == 1) ? Wk : ((z == 2) ? Wv : Wo));
    __half* dst      = (z == 0) ? dq : ((z == 1) ? dk : ((z == 2) ? dv : dwo));
    int bx = blockIdx.x * 32, by = blockIdx.y * 32;
    int tx = threadIdx.x, ty = threadIdx.y;
#pragma unroll
    for (int j = 0; j < 32; j += 8)
        tile[ty + j][tx] = src[(size_t)(by + ty + j) * DIMC + bx + tx];
    __syncthreads();
#pragma unroll
    for (int j = 0; j < 32; j += 8)
        dst[(size_t)(bx + ty + j) * DIMC + by + tx] =
            __float2half_rn(tile[tx][ty + j]);
}

// ---------------------------------------------------------------------------
// fp16 tensor-core GEMM (round-12 verbatim): C = A @ Bt^T + bias.
// CTA 128x128, K-step 32, 3-stage cp.async, ldmatrix both operands.
// 256 threads = 8 warps (2m x 4n), warp tile 64x32.
// ---------------------------------------------------------------------------
#define TS_H 40
#define TILE_H (128 * TS_H)
#define BUF_H (2 * TILE_H)
#define N_STAGE 3
#define GEMM_SMEM_BYTES (N_STAGE * BUF_H * 2)   // 61,440

__device__ __forceinline__ void gemm_tc(const __half* __restrict__ A,
                                        const __half* __restrict__ Bt,
                                        const float* __restrict__ bias,
                                        float* __restrict__ Cf,
                                        __half* __restrict__ Ch,
                                        int row0, int col0,
                                        __half* smh)
{
    const int tid  = threadIdx.x;
    const int lane = tid & 31;
    const int warp = tid >> 5;
    const int wm = warp >> 2;
    const int wn = warp & 3;
    const int r  = lane >> 2;
    const int c  = lane & 3;

    const int l16  = lane & 15;
    const int lh8  = (lane >> 4) << 3;

    const int st_row = tid >> 2;
    const int st_c   = (tid & 3) << 3;

    float acc[4][4][4];
#pragma unroll
    for (int mt = 0; mt < 4; mt++)
#pragma unroll
        for (int nt = 0; nt < 4; nt++)
#pragma unroll
            for (int i = 0; i < 4; i++) acc[mt][nt][i] = 0.f;

    auto issue_tile = [&](int kb, int buf) {
        unsigned abase = sptr(smh + buf * BUF_H);
        unsigned bbase = sptr(smh + buf * BUF_H + TILE_H);
#pragma unroll
        for (int p = 0; p < 2; p++) {
            int row  = st_row + p * 64;
            int grow = row0 + row;
            grow = (grow < S_TOK) ? grow : (S_TOK - 1);
            CP16(abase + (unsigned)(row * TS_H + st_c) * 2,
                 &A[(size_t)grow * DIMC + kb + st_c]);
            CP16(bbase + (unsigned)(row * TS_H + st_c) * 2,
                 &Bt[(size_t)(col0 + row) * DIMC + kb + st_c]);
        }
    };

    auto compute = [&](int buf) {
        const __half* As = smh + buf * BUF_H;
        const __half* Bs = As + TILE_H;
#pragma unroll
        for (int kk = 0; kk < 2; kk++) {
            uint4 a[4];
#pragma unroll
            for (int mt = 0; mt < 4; mt++)
                ldsm_x4(a[mt], sptr(&As[(wm * 64 + mt * 16 + l16) * TS_H
                                        + kk * 16 + lh8]));
            uint4 bb[2];
#pragma unroll
            for (int ntp = 0; ntp < 2; ntp++)
                ldsm_x4(bb[ntp], sptr(&Bs[(wn * 32 + ntp * 16 + l16) * TS_H
                                          + kk * 16 + lh8]));
#pragma unroll
            for (int mt = 0; mt < 4; mt++) {
                mma_f16(acc[mt][0], (const unsigned*)&a[mt], bb[0].x, bb[0].z);
                mma_f16(acc[mt][1], (const unsigned*)&a[mt], bb[0].y, bb[0].w);
                mma_f16(acc[mt][2], (const unsigned*)&a[mt], bb[1].x, bb[1].z);
                mma_f16(acc[mt][3], (const unsigned*)&a[mt], bb[1].y, bb[1].w);
            }
        }
    };

    const int NKB = DIMC / 32;
    issue_tile(0, 0);
    CP_COMMIT();
    issue_tile(32, 1);
    CP_COMMIT();
    for (int kb = 0; kb < NKB; kb++) {
        if (kb < NKB - 1) { CP_WAIT(1); } else { CP_WAIT(0); }
        __syncthreads();
        if (kb + 2 < NKB) {
            issue_tile((kb + 2) * 32, (kb + 2) % N_STAGE);
            CP_COMMIT();
        }
        compute(kb % N_STAGE);
    }

#pragma unroll
    for (int mt = 0; mt < 4; mt++) {
        int row_a = row0 + wm * 64 + mt * 16 + r;
        int row_b = row_a + 8;
#pragma unroll
        for (int nt = 0; nt < 4; nt++) {
            int col = col0 + wn * 32 + nt * 8 + 2 * c;
            float b0 = bias[col], b1 = bias[col + 1];
            float v0 = acc[mt][nt][0] + b0, v1 = acc[mt][nt][1] + b1;
            float v2 = acc[mt][nt][2] + b0, v3 = acc[mt][nt][3] + b1;
            if (Ch) {
                if (row_a < S_TOK)
                    *(__half2*)&Ch[(size_t)row_a * DIMC + col] =
                        __floats2half2_rn(v0, v1);
                if (row_b < S_TOK)
                    *(__half2*)&Ch[(size_t)row_b * DIMC + col] =
                        __floats2half2_rn(v2, v3);
            } else {
                if (row_a < S_TOK)
                    *(float2*)&Cf[(size_t)row_a * DIMC + col] = make_float2(v0, v1);
                if (row_b < S_TOK)
                    *(float2*)&Cf[(size_t)row_b * DIMC + col] = make_float2(v2, v3);
            }
        }
    }
}

__global__ void __launch_bounds__(256)
qkv_gemm(const float* __restrict__ bq, const float* __restrict__ bk,
         const float* __restrict__ bv)
{
    extern __shared__ __half smh[];
    int z = blockIdx.z;
    const __half* B    = (z == 0) ? g_wq : ((z == 1) ? g_wk : g_wv);
    const float* bias  = (z == 0) ? bq : ((z == 1) ? bk : bv);
    float*  Cf = (z == 0) ? g_q : ((z == 1) ? g_k : (float*)0);
    __half* Ch = (z == 2) ? g_v : (__half*)0;
    gemm_tc(g_xh, B, bias, Cf, Ch, blockIdx.y * 128, blockIdx.x * 128, smh);
}

__global__ void __launch_bounds__(256)
out_gemm(const float* __restrict__ bo, float* __restrict__ out)
{
    extern __shared__ __half smh[];
    gemm_tc(g_attn, g_wo, bo, out, (__half*)0,
            blockIdx.y * 128, blockIdx.x * 128, smh);
}

// ---------------------------------------------------------------------------
// Fused RMSNorm (full DIM) + 3D RoPE: g_q/g_k (fp32) -> g_qh/g_kh (fp16).
// ---------------------------------------------------------------------------
__global__ void norm_rope_kernel(const float* __restrict__ freqs,
                                 const float* __restrict__ gq,
                                 const float* __restrict__ gk)
{
    int s = blockIdx.x;
    int tid = threadIdx.x;
    const float* qrow = g_q + (size_t)s * DIMC;
    const float* krow = g_k + (size_t)s * DIMC;
    __half* qo = g_qh + (size_t)s * DIMC;
    __half* ko = g_kh + (size_t)s * DIMC;

    float2 qv[3], kv[3];
    float sq = 0.f, sk = 0.f;
#pragma unroll
    for (int p = 0; p < 3; p++) {
        int pr = tid + p * 256;
        qv[p] = *(const float2*)&qrow[2 * pr];
        kv[p] = *(const float2*)&krow[2 * pr];
        sq += qv[p].x * qv[p].x + qv[p].y * qv[p].y;
        sk += kv[p].x * kv[p].x + kv[p].y * kv[p].y;
    }
    __shared__ float red[2][8];
#pragma unroll
    for (int o = 16; o > 0; o >>= 1) {
        sq += __shfl_down_sync(0xffffffffu, sq, o);
        sk += __shfl_down_sync(0xffffffffu, sk, o);
    }
    int warp = tid >> 5;
    if ((tid & 31) == 0) { red[0][warp] = sq; red[1][warp] = sk; }
    __syncthreads();
    sq = 0.f; sk = 0.f;
#pragma unroll
    for (int w = 0; w < 8; w++) { sq += red[0][w]; sk += red[1][w]; }
    float rq = rsqrtf(sq * (1.f / DIMC) + 1e-6f);
    float rk = rsqrtf(sk * (1.f / DIMC) + 1e-6f);

    int f = s / FRAME;
    int rem = s % FRAME;
    int hh = rem / 28;
    int ww = rem % 28;
#pragma unroll
    for (int p = 0; p < 3; p++) {
        int pr = tid + p * 256;
        int rot = pr & 63;
        float a;
        if (rot < 22)       a = freqs[f  * ROTC + rot];
        else if (rot < 43)  a = freqs[hh * ROTC + rot];
        else                a = freqs[ww * ROTC + rot];
        float cc = cosf(a), sn = sinf(a);
        float q0 = qv[p].x * rq * gq[2 * pr];
        float q1 = qv[p].y * rq * gq[2 * pr + 1];
        float k0 = kv[p].x * rk * gk[2 * pr];
        float k1 = kv[p].y * rk * gk[2 * pr + 1];
        *(__half2*)&qo[2 * pr] =
            __floats2half2_rn(q0 * cc - q1 * sn, q0 * sn + q1 * cc);
        *(__half2*)&ko[2 * pr] =
            __floats2half2_rn(k0 * cc - k1 * sn, k0 * sn + k1 * cc);
    }
}

// ---------------------------------------------------------------------------
// Frame-causal flash attention, fp16 m16n8k16, DOUBLE-BUFFERED K/V cp.async.
// Block = (64 q-rows, head), 128 threads (4 warps, 16 q-rows each).
// Qs[64][136] (aliased by Ps[64][72]); Ks[2][64][136]; Vs[2][64][136].
// 87,040 B smem -> 2 CTAs/SM. 2 syncthreads per k-iteration.
// Group queue: K0,V0,K1,V1,...; at iter kt, K(kt+1),V(kt+1) stay in flight.
// ---------------------------------------------------------------------------
#define QS_H 136
#define PS_H 72
#define TILE_AH (64 * QS_H)                    // 8704 halves
#define QS_OFF 0
#define KS_OFF TILE_AH
#define VS_OFF (KS_OFF + 2 * TILE_AH)
#define ATTN_SMEM_H (VS_OFF + 2 * TILE_AH)     // 43,520 halves = 87,040 B

__global__ void __launch_bounds__(128)
attn_kernel()
{
    extern __shared__ __half ash[];
    __half* Qs = ash + QS_OFF;
    __half* Ps = ash + QS_OFF;     // alias (Qs dead after frag load)

    const int tid  = threadIdx.x;
    const int lane = tid & 31;
    const int w    = tid >> 5;
    const int r    = lane >> 2;
    const int c    = lane & 3;
    const int w16  = w * 16;
    const int l16  = lane & 15;
    const int lh8  = (lane >> 4) << 3;

    const int qb   = 62 - blockIdx.x;   // longest q-tiles first
    const int row0 = qb * 64;
    const int h    = blockIdx.y;
    const int ktiles = (row0 / FRAME + 1) * (FRAME / 64);
    const float scale = 0.08838834764831845f;

    auto issue_k = [&](int krow0, int buf) {
        unsigned kbase = sptr(ash + KS_OFF + buf * TILE_AH);
#pragma unroll
        for (int it = 0; it < 8; it++) {
            int idx = tid + it * 128;
            int rr = idx >> 4;
            int ch = (idx & 15) << 3;
            CP16(kbase + (unsigned)(rr * QS_H + ch) * 2,
                 &g_kh[(size_t)(krow0 + rr) * DIMC + h * HDIM + ch]);
        }
        CP_COMMIT();
    };
    auto issue_v = [&](int krow0, int buf) {
        unsigned vbase = sptr(ash + VS_OFF + buf * TILE_AH);
#pragma unroll
        for (int it = 0; it < 8; it++) {
            int idx = tid + it * 128;
            int rr = idx >> 4;
            int ch = (idx & 15) << 3;
            CP16(vbase + (unsigned)(rr * QS_H + ch) * 2,
                 &g_v[(size_t)(krow0 + rr) * DIMC + h * HDIM + ch]);
        }
        CP_COMMIT();
    };

    // Prologue: fill both buffers (ktiles >= 7 always)
    issue_k(0, 0);
    issue_v(0, 0);
    issue_k(64, 1);
    issue_v(64, 1);

    // Stage Q (plain copies, overlaps the cp.async groups)
#pragma unroll
    for (int it = 0; it < 8; it++) {
        int idx = tid + it * 128;
        int rr = idx >> 4;
        int ch = (idx & 15) << 3;
        *(uint4*)&Qs[rr * QS_H + ch] =
            *(const uint4*)&g_qh[(size_t)(row0 + rr) * DIMC + h * HDIM + ch];
    }
    __syncthreads();

    uint4 qa[8];
#pragma unroll
    for (int dt = 0; dt < 8; dt++)
        ldsm_x4(qa[dt], sptr(&Qs[(w16 + l16) * QS_H + dt * 16 + lh8]));

    float O[16][4];
#pragma unroll
    for (int nt = 0; nt < 16; nt++)
#pragma unroll
        for (int i = 0; i < 4; i++) O[nt][i] = 0.f;
    float m0 = -1e30f, m1 = -1e30f, l0 = 0.f, l1 = 0.f;

    for (int kt = 0; kt < ktiles; kt++) {
        const int cur = kt & 1;
        const __half* Ks = ash + KS_OFF + cur * TILE_AH;
        const __half* Vs = ash + VS_OFF + cur * TILE_AH;

        // Wait K(kt)+V(kt); K(kt+1),V(kt+1) stay in flight
        if (kt + 1 < ktiles) { CP_WAIT(2); } else { CP_WAIT(0); }
        __syncthreads();

        // S = Q K^T
        float S[8][4];
#pragma unroll
        for (int nt = 0; nt < 8; nt++)
#pragma unroll
            for (int i = 0; i < 4; i++) S[nt][i] = 0.f;
#pragma unroll
        for (int dt = 0; dt < 8; dt++) {
#pragma unroll
            for (int ng = 0; ng < 4; ng++) {
                uint4 kb;
                ldsm_x4(kb, sptr(&Ks[(ng * 16 + l16) * QS_H + dt * 16 + lh8]));
                mma_f16(S[2 * ng],     (const unsigned*)&qa[dt], kb.x, kb.z);
                mma_f16(S[2 * ng + 1], (const unsigned*)&qa[dt], kb.y, kb.w);
            }
        }

        // Online softmax
        float mx0 = -1e30f, mx1 = -1e30f;
#pragma unroll
        for (int nt = 0; nt < 8; nt++) {
            mx0 = fmaxf(mx0, fmaxf(S[nt][0], S[nt][1]));
            mx1 = fmaxf(mx1, fmaxf(S[nt][2], S[nt][3]));
        }
        mx0 = fmaxf(mx0, __shfl_xor_sync(0xffffffffu, mx0, 1));
        mx0 = fmaxf(mx0, __shfl_xor_sync(0xffffffffu, mx0, 2));
        mx1 = fmaxf(mx1, __shfl_xor_sync(0xffffffffu, mx1, 1));
        mx1 = fmaxf(mx1, __shfl_xor_sync(0xffffffffu, mx1, 2));
        float mn0 = fmaxf(m0, mx0), mn1 = fmaxf(m1, mx1);
        float fac0 = __expf((m0 - mn0) * scale);
        float fac1 = __expf((m1 - mn1) * scale);

        float sum0 = 0.f, sum1 = 0.f;
#pragma unroll
        for (int nt = 0; nt < 8; nt++) {
            float p00 = __expf((S[nt][0] - mn0) * scale);
            float p01 = __expf((S[nt][1] - mn0) * scale);
            float p10 = __expf((S[nt][2] - mn1) * scale);
            float p11 = __expf((S[nt][3] - mn1) * scale);
            sum0 += p00 + p01;
            sum1 += p10 + p11;
            *(__half2*)&Ps[(w16 + r) * PS_H + nt * 8 + 2 * c] =
                __floats2half2_rn(p00, p01);
            *(__half2*)&Ps[(w16 + r + 8) * PS_H + nt * 8 + 2 * c] =
                __floats2half2_rn(p10, p11);
        }
        sum0 += __shfl_xor_sync(0xffffffffu, sum0, 1);
        sum0 += __shfl_xor_sync(0xffffffffu, sum0, 2);
        sum1 += __shfl_xor_sync(0xffffffffu, sum1, 1);
        sum1 += __shfl_xor_sync(0xffffffffu, sum1, 2);
        l0 = l0 * fac0 + sum0;
        l1 = l1 * fac1 + sum1;
        m0 = mn0; m1 = mn1;

#pragma unroll
        for (int nt = 0; nt < 16; nt++) {
            O[nt][0] *= fac0; O[nt][1] *= fac0;
            O[nt][2] *= fac1; O[nt][3] *= fac1;
        }
        __syncwarp();   // Ps stores visible to warp lanes before ldmatrix

        // O += P V (V already resident in this buffer)
#pragma unroll
        for (int k16 = 0; k16 < 4; k16++) {
            uint4 pa;
            ldsm_x4(pa, sptr(&Ps[(w16 + l16) * PS_H + k16 * 16 + lh8]));
#pragma unroll
            for (int ntp = 0; ntp < 8; ntp++) {
                uint4 vb;
                ldsm_x4_t(vb, sptr(&Vs[(k16 * 16 + l16) * QS_H + ntp * 16 + lh8]));
                mma_f16(O[2 * ntp],     (const unsigned*)&pa, vb.x, vb.y);
                mma_f16(O[2 * ntp + 1], (const unsigned*)&pa, vb.z, vb.w);
            }
        }
        __syncthreads();   // all warps done reading Ks/Vs[cur] before refill
        if (kt + 2 < ktiles) {
            issue_k((kt + 2) * 64, cur);
            issue_v((kt + 2) * 64, cur);
        }
    }

    float inv0 = 1.f / l0, inv1 = 1.f / l1;
    int row_a = row0 + w16 + r;
    int row_b = row_a + 8;
#pragma unroll
    for (int nt = 0; nt < 16; nt++) {
        int col = h * HDIM + nt * 8 + 2 * c;
        *(__half2*)&g_attn[(size_t)row_a * DIMC + col] =
            __floats2half2_rn(O[nt][0] * inv0, O[nt][1] * inv0);
        *(__half2*)&g_attn[(size_t)row_b * DIMC + col] =
            __floats2half2_rn(O[nt][2] * inv1, O[nt][3] * inv1);
    }
}

// ---------------------------------------------------------------------------
extern "C" void kernel_launch(void* const* d_in, const int* in_sizes, int n_in,
                              void* d_out, int out_size)
{
    (void)in_sizes; (void)n_in; (void)out_size;
    const float* x     = (const float*)d_in[0];
    const float* freqs = (const float*)d_in[3];
    const float* Wq    = (const float*)d_in[4];
    const float* bq    = (const float*)d_in[5];
    const float* Wk    = (const float*)d_in[6];
    const float* bk    = (const float*)d_in[7];
    const float* Wv    = (const float*)d_in[8];
    const float* bv    = (const float*)d_in[9];
    const float* Wo    = (const float*)d_in[10];
    const float* bo    = (const float*)d_in[11];
    const float* gq    = (const float*)d_in[12];
    const float* gk    = (const float*)d_in[13];
    float* out = (float*)d_out;

    const int gemm_smem = GEMM_SMEM_BYTES;      // 61,440 B
    const int attn_smem = ATTN_SMEM_H * 2;      // 87,040 B
    cudaFuncSetAttribute(qkv_gemm,
                         cudaFuncAttributeMaxDynamicSharedMemorySize, gemm_smem);
    cudaFuncSetAttribute(out_gemm,
                         cudaFuncAttributeMaxDynamicSharedMemorySize, gemm_smem);
    cudaFuncSetAttribute(attn_kernel,
                         cudaFuncAttributeMaxDynamicSharedMemorySize, attn_smem);

    __half* dxh; __half* dwq; __half* dwk; __half* dwv; __half* dwo;
    cudaGetSymbolAddress((void**)&dxh, g_xh);
    cudaGetSymbolAddress((void**)&dwq, g_wq);
    cudaGetSymbolAddress((void**)&dwk, g_wk);
    cudaGetSymbolAddress((void**)&dwv, g_wv);
    cudaGetSymbolAddress((void**)&dwo, g_wo);
    const int NX4 = S_TOK * DIMC / 4;
    cvt_h_kernel<<<(NX4 + 255) / 256, 256>>>(x, dxh, NX4);
    cvt_tr4_kernel<<<dim3(DIMC / 32, DIMC / 32, 4), dim3(32, 8)>>>(
        Wq, Wk, Wv, Wo, dwq, dwk, dwv, dwo);

    qkv_gemm<<<dim3(12, 32, 3), 256, gemm_smem>>>(bq, bk, bv);
    norm_rope_kernel<<<S_TOK, 256>>>(freqs, gq, gk);
    attn_kernel<<<dim3(63, 12), 128, attn_smem>>>();
    out_gemm<<<dim3(12, 32), 256, gemm_smem>>>(bo, out);
}

// round 17
// speedup vs baseline: 1.1329x; 1.1329x over previous
#include <cuda_runtime.h>
#include <cuda_fp16.h>
#include <math.h>

#define S_TOK 4032
#define DIMC  1536
#define NHEAD 12
#define HDIM  128
#define ROTC  64
#define FRAME 448

// Scratch (device globals)
__device__ float  g_q[S_TOK * DIMC];        // fp32 Q projection (pre-norm)
__device__ float  g_k[S_TOK * DIMC];        // fp32 K projection (pre-norm)
__device__ __half g_qh[S_TOK * DIMC];       // fp16 roped Q
__device__ __half g_kh[S_TOK * DIMC];       // fp16 roped K
__device__ __half g_v[S_TOK * DIMC];        // fp16 V
__device__ __half g_attn[S_TOK * DIMC];     // fp16 attention output
__device__ __half g_xh[S_TOK * DIMC];       // fp16 x
__device__ __half g_wq[DIMC * DIMC];        // fp16 weights, TRANSPOSED [n][k]
__device__ __half g_wk[DIMC * DIMC];
__device__ __half g_wv[DIMC * DIMC];
__device__ __half g_wo[DIMC * DIMC];

// ---------------------------------------------------------------------------
// fp16 mma / ldmatrix / async helpers
// ---------------------------------------------------------------------------
__device__ __forceinline__ void mma_f16(float* d, const unsigned* a,
                                        unsigned b0, unsigned b1) {
    asm volatile(
        "mma.sync.aligned.m16n8k16.row.col.f32.f16.f16.f32 "
        "{%0,%1,%2,%3}, {%4,%5,%6,%7}, {%8,%9}, {%0,%1,%2,%3};\n"
        : "+f"(d[0]), "+f"(d[1]), "+f"(d[2]), "+f"(d[3])
        : "r"(a[0]), "r"(a[1]), "r"(a[2]), "r"(a[3]), "r"(b0), "r"(b1));
}
__device__ __forceinline__ void ldsm_x4(uint4& d, unsigned addr) {
    asm volatile("ldmatrix.sync.aligned.m8n8.x4.shared.b16 {%0,%1,%2,%3}, [%4];"
                 : "=r"(d.x), "=r"(d.y), "=r"(d.z), "=r"(d.w) : "r"(addr));
}
__device__ __forceinline__ void ldsm_x4_t(uint4& d, unsigned addr) {
    asm volatile("ldmatrix.sync.aligned.m8n8.x4.trans.shared.b16 {%0,%1,%2,%3}, [%4];"
                 : "=r"(d.x), "=r"(d.y), "=r"(d.z), "=r"(d.w) : "r"(addr));
}
__device__ __forceinline__ unsigned sptr(const void* p) {
    return (unsigned)__cvta_generic_to_shared(p);
}
#define CP16(dst, src) \
    asm volatile("cp.async.cg.shared.global [%0], [%1], 16;" :: "r"(dst), "l"(src))
#define CP_COMMIT() asm volatile("cp.async.commit_group;")
#define CP_WAIT(n)  asm volatile("cp.async.wait_group %0;" :: "n"(n))

// ---------------------------------------------------------------------------
// x: fp32 -> fp16 (elementwise)
// ---------------------------------------------------------------------------
__global__ void cvt_h_kernel(const float* __restrict__ src,
                             __half* __restrict__ dst, int n4)
{
    int i = blockIdx.x * blockDim.x + threadIdx.x;
    if (i < n4) {
        float4 v = ((const float4*)src)[i];
        ((__half2*)dst)[2 * i]     = __floats2half2_rn(v.x, v.y);
        ((__half2*)dst)[2 * i + 1] = __floats2half2_rn(v.z, v.w);
    }
}

// ---------------------------------------------------------------------------
// All 4 weights: transpose + fp16 in ONE launch. dst[n][k] = h(src[k][n]).
// ---------------------------------------------------------------------------
__global__ void cvt_tr4_kernel(const float* __restrict__ Wq,
                               const float* __restrict__ Wk,
                               const float* __restrict__ Wv,
                               const float* __restrict__ Wo,
                               __half* __restrict__ dq,
                               __half* __restrict__ dk,
                               __half* __restrict__ dv,
                               __half* __restrict__ dwo)
{
    __shared__ float tile[32][33];
    int z = blockIdx.z;
    const float* src = (z == 0) ? Wq : ((z == 1) ? Wk : ((z == 2) ? Wv : Wo));
    __half* dst      = (z == 0) ? dq : ((z == 1) ? dk : ((z == 2) ? dv : dwo));
    int bx = blockIdx.x * 32, by = blockIdx.y * 32;
    int tx = threadIdx.x, ty = threadIdx.y;
#pragma unroll
    for (int j = 0; j < 32; j += 8)
        tile[ty + j][tx] = src[(size_t)(by + ty + j) * DIMC + bx + tx];
    __syncthreads();
#pragma unroll
    for (int j = 0; j < 32; j += 8)
        dst[(size_t)(bx + ty + j) * DIMC + by + tx] =
            __float2half_rn(tile[tx][ty + j]);
}

// ---------------------------------------------------------------------------
// fp16 tensor-core GEMM (round-12 verbatim): C = A @ Bt^T + bias.
// CTA 128x128, K-step 32, 3-stage cp.async, ldmatrix both operands.
// 256 threads = 8 warps (2m x 4n), warp tile 64x32.
// ---------------------------------------------------------------------------
#define TS_H 40
#define TILE_H (128 * TS_H)
#define BUF_H (2 * TILE_H)
#define N_STAGE 3
#define GEMM_SMEM_BYTES (N_STAGE * BUF_H * 2)   // 61,440

__device__ __forceinline__ void gemm_tc(const __half* __restrict__ A,
                                        const __half* __restrict__ Bt,
                                        const float* __restrict__ bias,
                                        float* __restrict__ Cf,
                                        __half* __restrict__ Ch,
                                        int row0, int col0,
                                        __half* smh)
{
    const int tid  = threadIdx.x;
    const int lane = tid & 31;
    const int warp = tid >> 5;
    const int wm = warp >> 2;
    const int wn = warp & 3;
    const int r  = lane >> 2;
    const int c  = lane & 3;

    const int l16  = lane & 15;
    const int lh8  = (lane >> 4) << 3;

    const int st_row = tid >> 2;
    const int st_c   = (tid & 3) << 3;

    float acc[4][4][4];
#pragma unroll
    for (int mt = 0; mt < 4; mt++)
#pragma unroll
        for (int nt = 0; nt < 4; nt++)
#pragma unroll
            for (int i = 0; i < 4; i++) acc[mt][nt][i] = 0.f;

    auto issue_tile = [&](int kb, int buf) {
        unsigned abase = sptr(smh + buf * BUF_H);
        unsigned bbase = sptr(smh + buf * BUF_H + TILE_H);
#pragma unroll
        for (int p = 0; p < 2; p++) {
            int row  = st_row + p * 64;
            int grow = row0 + row;
            grow = (grow < S_TOK) ? grow : (S_TOK - 1);
            CP16(abase + (unsigned)(row * TS_H + st_c) * 2,
                 &A[(size_t)grow * DIMC + kb + st_c]);
            CP16(bbase + (unsigned)(row * TS_H + st_c) * 2,
                 &Bt[(size_t)(col0 + row) * DIMC + kb + st_c]);
        }
    };

    auto compute = [&](int buf) {
        const __half* As = smh + buf * BUF_H;
        const __half* Bs = As + TILE_H;
#pragma unroll
        for (int kk = 0; kk < 2; kk++) {
            uint4 a[4];
#pragma unroll
            for (int mt = 0; mt < 4; mt++)
                ldsm_x4(a[mt], sptr(&As[(wm * 64 + mt * 16 + l16) * TS_H
                                        + kk * 16 + lh8]));
            uint4 bb[2];
#pragma unroll
            for (int ntp = 0; ntp < 2; ntp++)
                ldsm_x4(bb[ntp], sptr(&Bs[(wn * 32 + ntp * 16 + l16) * TS_H
                                          + kk * 16 + lh8]));
#pragma unroll
            for (int mt = 0; mt < 4; mt++) {
                mma_f16(acc[mt][0], (const unsigned*)&a[mt], bb[0].x, bb[0].z);
                mma_f16(acc[mt][1], (const unsigned*)&a[mt], bb[0].y, bb[0].w);
                mma_f16(acc[mt][2], (const unsigned*)&a[mt], bb[1].x, bb[1].z);
                mma_f16(acc[mt][3], (const unsigned*)&a[mt], bb[1].y, bb[1].w);
            }
        }
    };

    const int NKB = DIMC / 32;
    issue_tile(0, 0);
    CP_COMMIT();
    issue_tile(32, 1);
    CP_COMMIT();
    for (int kb = 0; kb < NKB; kb++) {
        if (kb < NKB - 1) { CP_WAIT(1); } else { CP_WAIT(0); }
        __syncthreads();
        if (kb + 2 < NKB) {
            issue_tile((kb + 2) * 32, (kb + 2) % N_STAGE);
            CP_COMMIT();
        }
        compute(kb % N_STAGE);
    }

#pragma unroll
    for (int mt = 0; mt < 4; mt++) {
        int row_a = row0 + wm * 64 + mt * 16 + r;
        int row_b = row_a + 8;
#pragma unroll
        for (int nt = 0; nt < 4; nt++) {
            int col = col0 + wn * 32 + nt * 8 + 2 * c;
            float b0 = bias[col], b1 = bias[col + 1];
            float v0 = acc[mt][nt][0] + b0, v1 = acc[mt][nt][1] + b1;
            float v2 = acc[mt][nt][2] + b0, v3 = acc[mt][nt][3] + b1;
            if (Ch) {
                if (row_a < S_TOK)
                    *(__half2*)&Ch[(size_t)row_a * DIMC + col] =
                        __floats2half2_rn(v0, v1);
                if (row_b < S_TOK)
                    *(__half2*)&Ch[(size_t)row_b * DIMC + col] =
                        __floats2half2_rn(v2, v3);
            } else {
                if (row_a < S_TOK)
                    *(float2*)&Cf[(size_t)row_a * DIMC + col] = make_float2(v0, v1);
                if (row_b < S_TOK)
                    *(float2*)&Cf[(size_t)row_b * DIMC + col] = make_float2(v2, v3);
            }
        }
    }
}

__global__ void __launch_bounds__(256)
qkv_gemm(const float* __restrict__ bq, const float* __restrict__ bk,
         const float* __restrict__ bv)
{
    extern __shared__ __half smh[];
    int z = blockIdx.z;
    const __half* B    = (z == 0) ? g_wq : ((z == 1) ? g_wk : g_wv);
    const float* bias  = (z == 0) ? bq : ((z == 1) ? bk : bv);
    float*  Cf = (z == 0) ? g_q : ((z == 1) ? g_k : (float*)0);
    __half* Ch = (z == 2) ? g_v : (__half*)0;
    gemm_tc(g_xh, B, bias, Cf, Ch, blockIdx.y * 128, blockIdx.x * 128, smh);
}

__global__ void __launch_bounds__(256)
out_gemm(const float* __restrict__ bo, float* __restrict__ out)
{
    extern __shared__ __half smh[];
    gemm_tc(g_attn, g_wo, bo, out, (__half*)0,
            blockIdx.y * 128, blockIdx.x * 128, smh);
}

// ---------------------------------------------------------------------------
// Fused RMSNorm (full DIM) + 3D RoPE: g_q/g_k (fp32) -> g_qh/g_kh (fp16).
// ---------------------------------------------------------------------------
__global__ void norm_rope_kernel(const float* __restrict__ freqs,
                                 const float* __restrict__ gq,
                                 const float* __restrict__ gk)
{
    int s = blockIdx.x;
    int tid = threadIdx.x;
    const float* qrow = g_q + (size_t)s * DIMC;
    const float* krow = g_k + (size_t)s * DIMC;
    __half* qo = g_qh + (size_t)s * DIMC;
    __half* ko = g_kh + (size_t)s * DIMC;

    float2 qv[3], kv[3];
    float sq = 0.f, sk = 0.f;
#pragma unroll
    for (int p = 0; p < 3; p++) {
        int pr = tid + p * 256;
        qv[p] = *(const float2*)&qrow[2 * pr];
        kv[p] = *(const float2*)&krow[2 * pr];
        sq += qv[p].x * qv[p].x + qv[p].y * qv[p].y;
        sk += kv[p].x * kv[p].x + kv[p].y * kv[p].y;
    }
    __shared__ float red[2][8];
#pragma unroll
    for (int o = 16; o > 0; o >>= 1) {
        sq += __shfl_down_sync(0xffffffffu, sq, o);
        sk += __shfl_down_sync(0xffffffffu, sk, o);
    }
    int warp = tid >> 5;
    if ((tid & 31) == 0) { red[0][warp] = sq; red[1][warp] = sk; }
    __syncthreads();
    sq = 0.f; sk = 0.f;
#pragma unroll
    for (int w = 0; w < 8; w++) { sq += red[0][w]; sk += red[1][w]; }
    float rq = rsqrtf(sq * (1.f / DIMC) + 1e-6f);
    float rk = rsqrtf(sk * (1.f / DIMC) + 1e-6f);

    int f = s / FRAME;
    int rem = s % FRAME;
    int hh = rem / 28;
    int ww = rem % 28;
#pragma unroll
    for (int p = 0; p < 3; p++) {
        int pr = tid + p * 256;
        int rot = pr & 63;
        float a;
        if (rot < 22)       a = freqs[f  * ROTC + rot];
        else if (rot < 43)  a = freqs[hh * ROTC + rot];
        else                a = freqs[ww * ROTC + rot];
        float cc = cosf(a), sn = sinf(a);
        float q0 = qv[p].x * rq * gq[2 * pr];
        float q1 = qv[p].y * rq * gq[2 * pr + 1];
        float k0 = kv[p].x * rk * gk[2 * pr];
        float k1 = kv[p].y * rk * gk[2 * pr + 1];
        *(__half2*)&qo[2 * pr] =
            __floats2half2_rn(q0 * cc - q1 * sn, q0 * sn + q1 * cc);
        *(__half2*)&ko[2 * pr] =
            __floats2half2_rn(k0 * cc - k1 * sn, k0 * sn + k1 * cc);
    }
}

// ---------------------------------------------------------------------------
// Frame-causal flash attention, fp16 m16n8k16, cp.async phase-split prefetch.
// Block = (64 q-rows, head), 128 threads (4 warps, 16 q-rows each).
// Grid (12 heads, 63 qtiles), qb = 62 - blockIdx.y: linear launch order is
// qtile-major => ALL heads' longest tiles start first (global LPT).
// ---------------------------------------------------------------------------
#define QS_H 136
#define PS_H 72
#define QS_OFF 0
#define KS_OFF (64 * QS_H)
#define VS_OFF (2 * 64 * QS_H)
#define ATTN_SMEM_H (3 * 64 * QS_H)     // 52,224 B

__global__ void __launch_bounds__(128)
attn_kernel()
{
    extern __shared__ __half ash[];
    __half* Qs = ash + QS_OFF;
    __half* Ps = ash + QS_OFF;     // alias (Qs dead after frag load)
    __half* Ks = ash + KS_OFF;
    __half* Vs = ash + VS_OFF;

    const int tid  = threadIdx.x;
    const int lane = tid & 31;
    const int w    = tid >> 5;
    const int r    = lane >> 2;
    const int c    = lane & 3;
    const int w16  = w * 16;
    const int l16  = lane & 15;
    const int lh8  = (lane >> 4) << 3;

    const int qb   = 62 - blockIdx.y;   // qtile-major global LPT
    const int row0 = qb * 64;
    const int h    = blockIdx.x;
    const int ktiles = (row0 / FRAME + 1) * (FRAME / 64);
    const float scale = 0.08838834764831845f;

    auto issue_k = [&](int krow0) {
        unsigned kbase = sptr(Ks);
#pragma unroll
        for (int it = 0; it < 8; it++) {
            int idx = tid + it * 128;
            int rr = idx >> 4;
            int ch = (idx & 15) << 3;
            CP16(kbase + (unsigned)(rr * QS_H + ch) * 2,
                 &g_kh[(size_t)(krow0 + rr) * DIMC + h * HDIM + ch]);
        }
        CP_COMMIT();
    };
    auto issue_v = [&](int krow0) {
        unsigned vbase = sptr(Vs);
#pragma unroll
        for (int it = 0; it < 8; it++) {
            int idx = tid + it * 128;
            int rr = idx >> 4;
            int ch = (idx & 15) << 3;
            CP16(vbase + (unsigned)(rr * QS_H + ch) * 2,
                 &g_v[(size_t)(krow0 + rr) * DIMC + h * HDIM + ch]);
        }
        CP_COMMIT();
    };

    issue_k(0);
    issue_v(0);

#pragma unroll
    for (int it = 0; it < 8; it++) {
        int idx = tid + it * 128;
        int rr = idx >> 4;
        int ch = (idx & 15) << 3;
        *(uint4*)&Qs[rr * QS_H + ch] =
            *(const uint4*)&g_qh[(size_t)(row0 + rr) * DIMC + h * HDIM + ch];
    }
    __syncthreads();

    uint4 qa[8];
#pragma unroll
    for (int dt = 0; dt < 8; dt++)
        ldsm_x4(qa[dt], sptr(&Qs[(w16 + l16) * QS_H + dt * 16 + lh8]));

    float O[16][4];
#pragma unroll
    for (int nt = 0; nt < 16; nt++)
#pragma unroll
        for (int i = 0; i < 4; i++) O[nt][i] = 0.f;
    float m0 = -1e30f, m1 = -1e30f, l0 = 0.f, l1 = 0.f;

    for (int kt = 0; kt < ktiles; kt++) {
        CP_WAIT(1);
        __syncthreads();

        float S[8][4];
#pragma unroll
        for (int nt = 0; nt < 8; nt++)
#pragma unroll
            for (int i = 0; i < 4; i++) S[nt][i] = 0.f;
#pragma unroll
        for (int dt = 0; dt < 8; dt++) {
#pragma unroll
            for (int ng = 0; ng < 4; ng++) {
                uint4 kb;
                ldsm_x4(kb, sptr(&Ks[(ng * 16 + l16) * QS_H + dt * 16 + lh8]));
                mma_f16(S[2 * ng],     (const unsigned*)&qa[dt], kb.x, kb.z);
                mma_f16(S[2 * ng + 1], (const unsigned*)&qa[dt], kb.y, kb.w);
            }
        }
        __syncthreads();
        if (kt + 1 < ktiles) issue_k((kt + 1) * 64);

        float mx0 = -1e30f, mx1 = -1e30f;
#pragma unroll
        for (int nt = 0; nt < 8; nt++) {
            mx0 = fmaxf(mx0, fmaxf(S[nt][0], S[nt][1]));
            mx1 = fmaxf(mx1, fmaxf(S[nt][2], S[nt][3]));
        }
        mx0 = fmaxf(mx0, __shfl_xor_sync(0xffffffffu, mx0, 1));
        mx0 = fmaxf(mx0, __shfl_xor_sync(0xffffffffu, mx0, 2));
        mx1 = fmaxf(mx1, __shfl_xor_sync(0xffffffffu, mx1, 1));
        mx1 = fmaxf(mx1, __shfl_xor_sync(0xffffffffu, mx1, 2));
        float mn0 = fmaxf(m0, mx0), mn1 = fmaxf(m1, mx1);
        float fac0 = __expf((m0 - mn0) * scale);
        float fac1 = __expf((m1 - mn1) * scale);

        float sum0 = 0.f, sum1 = 0.f;
#pragma unroll
        for (int nt = 0; nt < 8; nt++) {
            float p00 = __expf((S[nt][0] - mn0) * scale);
            float p01 = __expf((S[nt][1] - mn0) * scale);
            float p10 = __expf((S[nt][2] - mn1) * scale);
            float p11 = __expf((S[nt][3] - mn1) * scale);
            sum0 += p00 + p01;
            sum1 += p10 + p11;
            *(__half2*)&Ps[(w16 + r) * PS_H + nt * 8 + 2 * c] =
                __floats2half2_rn(p00, p01);
            *(__half2*)&Ps[(w16 + r + 8) * PS_H + nt * 8 + 2 * c] =
                __floats2half2_rn(p10, p11);
        }
        sum0 += __shfl_xor_sync(0xffffffffu, sum0, 1);
        sum0 += __shfl_xor_sync(0xffffffffu, sum0, 2);
        sum1 += __shfl_xor_sync(0xffffffffu, sum1, 1);
        sum1 += __shfl_xor_sync(0xffffffffu, sum1, 2);
        l0 = l0 * fac0 + sum0;
        l1 = l1 * fac1 + sum1;
        m0 = mn0; m1 = mn1;

#pragma unroll
        for (int nt = 0; nt < 16; nt++) {
            O[nt][0] *= fac0; O[nt][1] *= fac0;
            O[nt][2] *= fac1; O[nt][3] *= fac1;
        }

        if (kt + 1 < ktiles) { CP_WAIT(1); } else { CP_WAIT(0); }
        __syncthreads();

#pragma unroll
        for (int k16 = 0; k16 < 4; k16++) {
            uint4 pa;
            ldsm_x4(pa, sptr(&Ps[(w16 + l16) * PS_H + k16 * 16 + lh8]));
#pragma unroll
            for (int ntp = 0; ntp < 8; ntp++) {
                uint4 vb;
                ldsm_x4_t(vb, sptr(&Vs[(k16 * 16 + l16) * QS_H + ntp * 16 + lh8]));
                mma_f16(O[2 * ntp],     (const unsigned*)&pa, vb.x, vb.y);
                mma_f16(O[2 * ntp + 1], (const unsigned*)&pa, vb.z, vb.w);
            }
        }
        __syncthreads();
        if (kt + 1 < ktiles) issue_v((kt + 1) * 64);
    }

    float inv0 = 1.f / l0, inv1 = 1.f / l1;
    int row_a = row0 + w16 + r;
    int row_b = row_a + 8;
#pragma unroll
    for (int nt = 0; nt < 16; nt++) {
        int col = h * HDIM + nt * 8 + 2 * c;
        *(__half2*)&g_attn[(size_t)row_a * DIMC + col] =
            __floats2half2_rn(O[nt][0] * inv0, O[nt][1] * inv0);
        *(__half2*)&g_attn[(size_t)row_b * DIMC + col] =
            __floats2half2_rn(O[nt][2] * inv1, O[nt][3] * inv1);
    }
}

// ---------------------------------------------------------------------------
extern "C" void kernel_launch(void* const* d_in, const int* in_sizes, int n_in,
                              void* d_out, int out_size)
{
    (void)in_sizes; (void)n_in; (void)out_size;
    const float* x     = (const float*)d_in[0];
    const float* freqs = (const float*)d_in[3];
    const float* Wq    = (const float*)d_in[4];
    const float* bq    = (const float*)d_in[5];
    const float* Wk    = (const float*)d_in[6];
    const float* bk    = (const float*)d_in[7];
    const float* Wv    = (const float*)d_in[8];
    const float* bv    = (const float*)d_in[9];
    const float* Wo    = (const float*)d_in[10];
    const float* bo    = (const float*)d_in[11];
    const float* gq    = (const float*)d_in[12];
    const float* gk    = (const float*)d_in[13];
    float* out = (float*)d_out;

    const int gemm_smem = GEMM_SMEM_BYTES;      // 61,440 B
    const int attn_smem = ATTN_SMEM_H * 2;      // 52,224 B
    cudaFuncSetAttribute(qkv_gemm,
                         cudaFuncAttributeMaxDynamicSharedMemorySize, gemm_smem);
    cudaFuncSetAttribute(out_gemm,
                         cudaFuncAttributeMaxDynamicSharedMemorySize, gemm_smem);
    cudaFuncSetAttribute(attn_kernel,
                         cudaFuncAttributeMaxDynamicSharedMemorySize, attn_smem);

    __half* dxh; __half* dwq; __half* dwk; __half* dwv; __half* dwo;
    cudaGetSymbolAddress((void**)&dxh, g_xh);
    cudaGetSymbolAddress((void**)&dwq, g_wq);
    cudaGetSymbolAddress((void**)&dwk, g_wk);
    cudaGetSymbolAddress((void**)&dwv, g_wv);
    cudaGetSymbolAddress((void**)&dwo, g_wo);
    const int NX4 = S_TOK * DIMC / 4;
    cvt_h_kernel<<<(NX4 + 255) / 256, 256>>>(x, dxh, NX4);
    cvt_tr4_kernel<<<dim3(DIMC / 32, DIMC / 32, 4), dim3(32, 8)>>>(
        Wq, Wk, Wv, Wo, dwq, dwk, dwv, dwo);

    qkv_gemm<<<dim3(12, 32, 3), 256, gemm_smem>>>(bq, bk, bv);
    norm_rope_kernel<<<S_TOK, 256>>>(freqs, gq, gk);
    attn_kernel<<<dim3(12, 63), 128, attn_smem>>>();
    out_gemm<<<dim3(12, 32), 256, gemm_smem>>>(bo, out);
}